// round 9
// baseline (speedup 1.0000x reference)
#include <cuda_runtime.h>

// Problem constants
#define BATCH   4
#define NPTS    16384
#define HALF    8192
#define FDIM    32
#define GD      16               // cells per axis (in CDF/u-space)
#define NC      (GD*GD*GD)       // 4096 cells per batch

typedef unsigned int u32;
typedef unsigned long long u64;

// Output layout (concatenated tuple, float32)
#define OFF_VPC   0
#define OFF_VFEAT (BATCH * HALF * 3)                  // 98304
#define OFF_NIDX  (OFF_VFEAT + BATCH * HALF * FDIM)   // 1146880
#define OFF_RNDS  (OFF_NIDX + BATCH * HALF)           // 1179648

// Cell boundaries in x-space: standard normal quantiles Phi^-1(i/16).
__constant__ float c_bnd[GD + 1] = {
    -1e30f,
    -1.5341206f, -1.1503494f, -0.8871466f, -0.6744898f,
    -0.4887764f, -0.3186394f, -0.1573107f,  0.0f,
     0.1573107f,  0.3186394f,  0.4887764f,  0.6744898f,
     0.8871466f,  1.1503494f,  1.5341206f,
     1e30f
};

// ---------------------------------------------------------------------------
// Scratch (device globals; no allocation allowed)
// ---------------------------------------------------------------------------
__device__ float4 g_valid[BATCH][HALF];
__device__ float4 g_query[BATCH][HALF];
__device__ int    g_pcell[BATCH][HALF];
__device__ int    g_qcell[BATCH][HALF];
__device__ int    g_cnt[2][BATCH][NC];
__device__ int    g_off[2][BATCH][NC+1];
__device__ int    g_cur[2][BATCH][NC];
__device__ float4 g_spt[BATCH][HALF];     // cell-sorted points (2x,2y,2z,p2)
__device__ int    g_sid[BATCH][HALF];     // original point index
__device__ float4 g_sq[BATCH][HALF];      // cell-sorted queries (x,y,z,q2)
__device__ int    g_sqid[BATCH][HALF];
__device__ int    g_sqc[BATCH][HALF];

// ||v||^2 left-to-right, no FMA contraction (match jax fp32 semantics)
__device__ __forceinline__ float sq3(float x, float y, float z) {
    return __fadd_rn(__fadd_rn(__fmul_rn(x, x), __fmul_rn(y, y)), __fmul_rn(z, z));
}

__device__ __forceinline__ int axis_cell(float x) {
    float u = __fmaf_rn(erff(x * 0.70710678f), 0.5f, 0.5f);
    int c = (int)(u * (float)GD);
    return max(0, min(GD - 1, c));
}
__device__ __forceinline__ int cell_of(float x, float y, float z) {
    return (axis_cell(z) * GD + axis_cell(y)) * GD + axis_cell(x);
}

// Order-preserving float->u32 encode (monotone for all finite floats + inf)
__device__ __forceinline__ u32 fenc32(float f) {
    u32 u = __float_as_uint(f);
    return u ^ ((u32)((int)u >> 31) | 0x80000000u);
}
__device__ __forceinline__ float fdec32(u32 e) {
    u32 u = (e & 0x80000000u) ? (e ^ 0x80000000u) : ~e;
    return __uint_as_float(u);
}

// Key = (enc(d2) << 32) | id. u64 order == (d2, id) lexicographic ==
// stable top_k comparator (smaller dist first, then smaller original index).
// Same id => same d2 (deterministic formula) => identical key, so dedup is
// plain key equality.
#define KINF (((u64)0xFF800000u << 32) | 0xFFFFFFFFu)   // enc(+inf), id=-1

__device__ __forceinline__ void ins2k(u64 k, u64& k1, u64& k2) {
    if (k == k1 || k == k2) return;
    if (k < k1) { k2 = k1; k1 = k; }
    else if (k < k2) { k2 = k; }
}

// Warp top-2: u64 min reduce, then min excluding the winner's key.
// (lane k1 != k1g => different id, so (k1==k1g)?k2:k1 represents exactly the
// lane's best candidate with id != winner-id; duplicates collapse by key.)
__device__ __forceinline__ void warp_reduce_top2k(u64& k1, u64& k2) {
    u64 k1g = k1;
#pragma unroll
    for (int o = 16; o > 0; o >>= 1)
        k1g = min(k1g, __shfl_xor_sync(0xFFFFFFFFu, k1g, o));
    u64 cand = (k1 == k1g) ? k2 : k1;
#pragma unroll
    for (int o = 16; o > 0; o >>= 1)
        cand = min(cand, __shfl_xor_sync(0xFFFFFFFFu, cand, o));
    k1 = k1g; k2 = cand;
}

// exact reference-rounded candidate scoring
__device__ __forceinline__ float score(float qx, float qy, float qz, float q2,
                                       float4 P) {
    float dot2 = __fadd_rn(__fadd_rn(__fmul_rn(qx, P.x), __fmul_rn(qy, P.y)),
                           __fmul_rn(qz, P.z));
    return __fsub_rn(__fadd_rn(q2, P.w), dot2);
}

// ---------------------------------------------------------------------------
// K0: zero histograms
// ---------------------------------------------------------------------------
__global__ void init_kernel() {
    int i = blockIdx.x * blockDim.x + threadIdx.x;
    if (i < 2 * BATCH * NC) ((int*)g_cnt)[i] = 0;
}

// ---------------------------------------------------------------------------
// K1: gathers + binning + histogram
// ---------------------------------------------------------------------------
__global__ void gather_kernel(const float* __restrict__ pc,
                              const float4* __restrict__ feats4,
                              const int* __restrict__ rnds,
                              float* __restrict__ out) {
    int i = blockIdx.x * blockDim.x + threadIdx.x;
    const int WF = BATCH * HALF * 8;
    const int WP = BATCH * HALF;

    if (i < WF) {
        int c = i & 7;
        int t = (i >> 3) & (HALF - 1);
        int b = i >> 16;
        int v = rnds[t];
        float4 val = feats4[(b * NPTS + v) * 8 + c];
        ((float4*)(out + OFF_VFEAT))[(b * HALF + t) * 8 + c] = val;
        return;
    }
    i -= WF;
    if (i < WP) {
        int t = i & (HALF - 1);
        int b = i >> 13;
        int v = rnds[t];
        int base = (b * NPTS + v) * 3;
        float x = pc[base + 0], y = pc[base + 1], z = pc[base + 2];
        int ob = OFF_VPC + (b * HALF + t) * 3;
        out[ob + 0] = x; out[ob + 1] = y; out[ob + 2] = z;
        g_valid[b][t] = make_float4(2.0f * x, 2.0f * y, 2.0f * z, sq3(x, y, z));
        int cid = cell_of(x, y, z);
        g_pcell[b][t] = cid;
        atomicAdd(&g_cnt[0][b][cid], 1);
        return;
    }
    i -= WP;
    if (i < WP) {
        int t = i & (HALF - 1);
        int b = i >> 13;
        int v = rnds[HALF + t];
        int base = (b * NPTS + v) * 3;
        float x = pc[base + 0], y = pc[base + 1], z = pc[base + 2];
        g_query[b][t] = make_float4(x, y, z, sq3(x, y, z));
        int cid = cell_of(x, y, z);
        g_qcell[b][t] = cid;
        atomicAdd(&g_cnt[1][b][cid], 1);
        return;
    }
    i -= WP;
    if (i < NPTS) out[OFF_RNDS + i] = (float)rnds[i];
}

// ---------------------------------------------------------------------------
// K2: exclusive scan via two-level warp shuffle scan
// ---------------------------------------------------------------------------
__global__ void __launch_bounds__(1024) scan_kernel() {
    int kind = blockIdx.x >> 2;
    int b = blockIdx.x & 3;
    const int CPT = NC / 1024;  // 4
    int tid = threadIdx.x;
    int lane = tid & 31;
    int wid = tid >> 5;

    int loc[CPT];
    int s = 0;
    const int* cnt = g_cnt[kind][b];
#pragma unroll
    for (int j = 0; j < CPT; ++j) { loc[j] = s; s += cnt[tid * CPT + j]; }

    int inc = s;
#pragma unroll
    for (int o = 1; o < 32; o <<= 1) {
        int v = __shfl_up_sync(0xFFFFFFFFu, inc, o);
        if (lane >= o) inc += v;
    }
    __shared__ int wsum[32];
    if (lane == 31) wsum[wid] = inc;
    __syncthreads();
    if (wid == 0) {
        int v = wsum[lane];
        int wi = v;
#pragma unroll
        for (int o = 1; o < 32; o <<= 1) {
            int u = __shfl_up_sync(0xFFFFFFFFu, wi, o);
            if (lane >= o) wi += u;
        }
        wsum[lane] = wi - v;
    }
    __syncthreads();
    int base = wsum[wid] + (inc - s);

    int* off_arr = g_off[kind][b];
    int* cur_arr = g_cur[kind][b];
#pragma unroll
    for (int j = 0; j < CPT; ++j) {
        int v = base + loc[j];
        off_arr[tid * CPT + j] = v;
        cur_arr[tid * CPT + j] = v;
    }
    if (tid == 1023) off_arr[NC] = base + s;
}

// ---------------------------------------------------------------------------
// K3: scatter into cell-sorted order
// ---------------------------------------------------------------------------
__global__ void scatter_kernel() {
    int i = blockIdx.x * blockDim.x + threadIdx.x;
    if (i >= 2 * BATCH * HALF) return;
    int kind = i >> 15;
    int b = (i >> 13) & (BATCH - 1);
    int t = i & (HALF - 1);
    if (kind == 0) {
        int cid = g_pcell[b][t];
        int pos = atomicAdd(&g_cur[0][b][cid], 1);
        g_spt[b][pos] = g_valid[b][t];
        g_sid[b][pos] = t;
    } else {
        int cid = g_qcell[b][t];
        int pos = atomicAdd(&g_cur[1][b][cid], 1);
        g_sq[b][pos] = g_query[b][t];
        g_sqid[b][pos] = t;
        g_sqc[b][pos] = cid;
    }
}

// ---------------------------------------------------------------------------
// K4: warp-per-query KNN. Query-adaptive 4x4x4 window (phase 1), 5x5x5 box
// (phase 2, key-dedup handles overlap), full brute-force fallback (phase 3).
// Run-based cooperative scan: window rows are contiguous point ranges; lanes
// fetch run extents, warp-scan lengths, all 32 lanes stride the concatenated
// candidates (coalesced). ids loaded lazily (enc(d2) <= high32(k2) required
// for any insertion, even ties). All scoring uses the exact reference-rounded
// formula; u64 key order == stable top_k comparator => bit-identical result.
// ---------------------------------------------------------------------------
__device__ __forceinline__ void scan_window(int x0, int x1, int y0, int y1,
                                            int z0, int z1,
                                            float qx, float qy, float qz, float q2,
                                            const float4* __restrict__ pts,
                                            const int* __restrict__ ids,
                                            const int* __restrict__ offs,
                                            int lane, u64& k1, u64& k2) {
    int NY = y1 - y0 + 1;
    int NR = NY * (z1 - z0 + 1);   // <= 25
    int p0 = 0, len = 0;
    if (lane < NR) {
        int cy = y0 + lane % NY;
        int cz = z0 + lane / NY;
        int rowbase = (cz * GD + cy) * GD;
        p0 = __ldg(&offs[rowbase + x0]);
        len = __ldg(&offs[rowbase + x1 + 1]) - p0;
    }
    // warp inclusive scan of len (lanes >= NR have len 0 -> excl == T)
    int inc = len;
#pragma unroll
    for (int o = 1; o < 32; o <<= 1) {
        int v = __shfl_up_sync(0xFFFFFFFFu, inc, o);
        if (lane >= o) inc += v;
    }
    int excl = inc - len;
    int T = __shfl_sync(0xFFFFFFFFu, inc, 31);  // total (lanes>=NR carry it)

    u32 b2hi = (u32)(k2 >> 32);
    for (int base = 0; base < T; base += 32) {
        int c = base + lane;
        bool active = c < T;
        int cc = active ? c : (T - 1);
        // largest run k with excl_k <= cc  (empty runs self-exclude)
        int lo = 0;
#pragma unroll
        for (int step = 16; step > 0; step >>= 1) {
            int mid = lo + step;
            int v = __shfl_sync(0xFFFFFFFFu, excl, min(mid, 31));
            if (mid < 32 && v <= cc) lo = mid;
        }
        int rp0 = __shfl_sync(0xFFFFFFFFu, p0, lo);
        int rex = __shfl_sync(0xFFFFFFFFu, excl, lo);
        int p = rp0 + (cc - rex);
        float4 P = pts[p];
        if (active) {
            u32 encd = fenc32(score(qx, qy, qz, q2, P));
            if (encd <= b2hi) {       // lazy id load; ties still admitted
                ins2k(((u64)encd << 32) | (u32)ids[p], k1, k2);
                b2hi = (u32)(k2 >> 32);
            }
        }
    }
    warp_reduce_top2k(k1, k2);
}

// warp-uniform: can any cell outside window [x0..x1]x[y0..y1]x[z0..z1] beat k2?
__device__ __forceinline__ bool term_ok_w(int x0, int x1, int y0, int y1,
                                          int z0, int z1,
                                          float qx, float qy, float qz,
                                          u64 k2, const float* sbnd) {
    const float INF = __int_as_float(0x7f800000);
    float bd2 = fdec32((u32)(k2 >> 32));
    if (!(bd2 < INF)) return false;
    float lb = INF;
    if (x0 > 0)      lb = fminf(lb, qx - sbnd[x0]);
    if (x1 < GD - 1) lb = fminf(lb, sbnd[x1 + 1] - qx);
    if (y0 > 0)      lb = fminf(lb, qy - sbnd[y0]);
    if (y1 < GD - 1) lb = fminf(lb, sbnd[y1 + 1] - qy);
    if (z0 > 0)      lb = fminf(lb, qz - sbnd[z0]);
    if (z1 < GD - 1) lb = fminf(lb, sbnd[z1 + 1] - qz);
    float lba = fmaxf(lb - 1e-5f, 0.0f);
    return lba * lba > bd2 * 1.001f + 1e-4f;
}

__global__ void __launch_bounds__(256) knn_kernel(float* __restrict__ out) {
    __shared__ float sbnd[GD + 1];
    if (threadIdx.x < GD + 1) sbnd[threadIdx.x] = c_bnd[threadIdx.x];
    __syncthreads();

    int w = (blockIdx.x * blockDim.x + threadIdx.x) >> 5;
    int lane = threadIdx.x & 31;
    int b = w >> 13;
    int s = w & (HALF - 1);

    float4 q = g_sq[b][s];
    int qi = g_sqid[b][s];
    int qc = g_sqc[b][s];
    const float qx = q.x, qy = q.y, qz = q.z, q2 = q.w;

    int qcx = qc & (GD - 1);
    int qcy = (qc >> 4) & (GD - 1);
    int qcz = qc >> 8;

    u64 k1 = KINF, k2 = KINF;

    const float4* __restrict__ pts = g_spt[b];
    const int* __restrict__ ids = g_sid[b];
    const int* __restrict__ offs = g_off[0][b];

    // Phase 1: query-adaptive 4-cell window per axis (within [qc-2, qc+2])
    int x0, x1, y0, y1, z0, z1;
    {
        bool lowx = (qx - sbnd[qcx]) < (sbnd[qcx + 1] - qx);
        x0 = max(qcx - (lowx ? 2 : 1), 0);
        x1 = min(qcx + (lowx ? 1 : 2), GD - 1);
        bool lowy = (qy - sbnd[qcy]) < (sbnd[qcy + 1] - qy);
        y0 = max(qcy - (lowy ? 2 : 1), 0);
        y1 = min(qcy + (lowy ? 1 : 2), GD - 1);
        bool lowz = (qz - sbnd[qcz]) < (sbnd[qcz + 1] - qz);
        z0 = max(qcz - (lowz ? 2 : 1), 0);
        z1 = min(qcz + (lowz ? 1 : 2), GD - 1);
    }
    scan_window(x0, x1, y0, y1, z0, z1, qx, qy, qz, q2, pts, ids, offs,
                lane, k1, k2);

    if (!term_ok_w(x0, x1, y0, y1, z0, z1, qx, qy, qz, k2, sbnd)) {
        // Phase 2: full 5x5x5 box (superset of phase-1 window; dedup by key)
        int X0 = max(qcx - 2, 0), X1 = min(qcx + 2, GD - 1);
        int Y0 = max(qcy - 2, 0), Y1 = min(qcy + 2, GD - 1);
        int Z0 = max(qcz - 2, 0), Z1 = min(qcz + 2, GD - 1);
        scan_window(X0, X1, Y0, Y1, Z0, Z1, qx, qy, qz, q2, pts, ids, offs,
                    lane, k1, k2);

        if (!term_ok_w(X0, X1, Y0, Y1, Z0, Z1, qx, qy, qz, k2, sbnd)) {
            // Phase 3: bounded fallback — full warp-parallel brute force
            u32 b2hi = (u32)(k2 >> 32);
            for (int p = lane; p < HALF; p += 32) {
                u32 encd = fenc32(score(qx, qy, qz, q2, pts[p]));
                if (encd <= b2hi) {
                    ins2k(((u64)encd << 32) | (u32)ids[p], k1, k2);
                    b2hi = (u32)(k2 >> 32);
                }
            }
            warp_reduce_top2k(k1, k2);
        }
    }

    if (lane == 0)
        out[OFF_NIDX + (b << 13) + qi] = (float)(int)(u32)(k2 & 0xFFFFFFFFu);
}

// ---------------------------------------------------------------------------
extern "C" void kernel_launch(void* const* d_in, const int* in_sizes, int n_in,
                              void* d_out, int out_size) {
    const float*  pc    = (const float*)d_in[0];
    const float4* feats = (const float4*)d_in[1];
    const int*    rnds  = (const int*)d_in[2];
    float*        out   = (float*)d_out;
    (void)in_sizes; (void)n_in; (void)out_size;

    init_kernel<<<(2 * BATCH * NC + 255) / 256, 256>>>();

    const int total = BATCH * HALF * 8 + 2 * BATCH * HALF + NPTS;  // 344064
    gather_kernel<<<total / 256, 256>>>(pc, feats, rnds, out);

    scan_kernel<<<2 * BATCH, 1024>>>();
    scatter_kernel<<<(2 * BATCH * HALF + 255) / 256, 256>>>();

    knn_kernel<<<BATCH * HALF * 32 / 256, 256>>>(out);
}